// round 5
// baseline (speedup 1.0000x reference)
#include <cuda_runtime.h>
#include <cuda_fp16.h>
#include <cstdint>

// jordon_combined_layer: out[b] = ob + sum_u sigmoid(x[b,:]@W[:,u] + bias[u] + state*state_W[u]) * oW[u]
// B = 2097152, D = U = 64, L = 1. Output fp32 [B,1].
//
// R5: R4 was L1tex-bound (89.6%) from the per-lane fragment-gather LDGs (8 lines
// per warp instr). Fix: coalesced cp.async.cg staging into double-buffered SMEM
// (padded stride 68 floats -> max 2-way LDS conflicts), fragments gathered via
// LDS.64. MMA (m16n8k16 f16, HMMA) and fused tanh-sigmoid epilogue unchanged.

#define ITERS          8
#define TILE_ROWS      64                     // rows per pipeline stage
#define ROWS_PER_CTA   (ITERS * TILE_ROWS)    // 512
#define XPAD           68                     // padded row stride (floats)

#define MMA16816(c0, c1, c2, c3, a0, a1, a2, a3, b0, b1)                         \
    asm volatile(                                                                \
        "mma.sync.aligned.m16n8k16.row.col.f32.f16.f16.f32 "                     \
        "{%0,%1,%2,%3}, {%4,%5,%6,%7}, {%8,%9}, {%0,%1,%2,%3};"                  \
        : "+f"(c0), "+f"(c1), "+f"(c2), "+f"(c3)                                 \
        : "r"(a0), "r"(a1), "r"(a2), "r"(a3), "r"(b0), "r"(b1))

#define CP_ASYNC16(dst_u32, src_ptr)                                             \
    asm volatile("cp.async.cg.shared.global [%0], [%1], 16;"                     \
                 :: "r"(dst_u32), "l"(src_ptr) : "memory")
#define CP_COMMIT()  asm volatile("cp.async.commit_group;" ::: "memory")
#define CP_WAIT(n)   asm volatile("cp.async.wait_group %0;" :: "n"(n) : "memory")

static __device__ __forceinline__ uint32_t h2bits(__half2 h) {
    return *reinterpret_cast<uint32_t*>(&h);
}

static __device__ __forceinline__ uint32_t smem_u32(const void* p) {
    return (uint32_t)__cvta_generic_to_shared(p);
}

__global__ void __launch_bounds__(128)
jordon_kernel(const float* __restrict__ x,
              const float* __restrict__ state,
              const float* __restrict__ inW,
              const float* __restrict__ stW,
              const float* __restrict__ bias,
              const float* __restrict__ outW,
              const float* __restrict__ outb,
              float* __restrict__ out) {
    // x staging: 2 buffers x 64 rows x 68 floats (padded) = 34816 B
    __shared__ float  xs[2][TILE_ROWS * XPAD];
    // W fragment table: [k-step][n-tile][lane] -> {b0, b1} (half2 bit patterns)
    __shared__ uint2  btab[4][8][32];
    // per-(n-tile, tg) constants: {0.5*(b+s)_u0, 0.5*oW_u0, 0.5*(b+s)_u1, 0.5*oW_u1}
    __shared__ float4 cwv[32];
    __shared__ float  ob;

    const int tid  = threadIdx.x;
    const int wid  = tid >> 5;
    const int lane = tid & 31;
    const int g    = lane >> 2;   // fragment row within 8
    const int tg   = lane & 3;    // thread-in-group (col pair)

    const float* xbase = x + (size_t)blockIdx.x * ROWS_PER_CTA * 64;

    // ---- issue tile 0 loads immediately (coalesced 16B cp.async) ----
    {
        const float* src = xbase;
#pragma unroll
        for (int t = 0; t < 8; t++) {
            int i  = tid + t * 128;          // 1024 float4 per tile
            int r  = i >> 4;
            int c4 = i & 15;
            CP_ASYNC16(smem_u32(&xs[0][r * XPAD + c4 * 4]), src + r * 64 + c4 * 4);
        }
        CP_COMMIT();
    }

    // ---- prologue: constants ----
    if (tid < 32) {
        int j  = tid >> 2;
        int t4 = tid & 3;
        int u0 = j * 8 + t4 * 2;
        float s  = state[0];
        float s0 = s * stW[u0];
        float s1 = s * stW[u0 + 1];
        cwv[tid] = make_float4(0.5f * (bias[u0] + s0),     0.5f * outW[u0],
                               0.5f * (bias[u0 + 1] + s1), 0.5f * outW[u0 + 1]);
    }
    if (tid == 32) ob = outb[0];

    // ---- prologue: W fragment table (warp 0 only; lane-indexed, warp-invariant) ----
    if (wid == 0) {
#pragma unroll
        for (int k = 0; k < 4; k++) {
#pragma unroll
            for (int j = 0; j < 8; j++) {
                int r = k * 16 + tg * 2;   // K index
                int c = j * 8 + g;         // N index (u)
                __half2 lo = __floats2half2_rn(inW[(r    ) * 64 + c], inW[(r + 1) * 64 + c]);
                __half2 hi = __floats2half2_rn(inW[(r + 8) * 64 + c], inW[(r + 9) * 64 + c]);
                btab[k][j][lane] = make_uint2(h2bits(lo), h2bits(hi));
            }
        }
    }

#pragma unroll 1
    for (int it = 0; it < ITERS; it++) {
        // issue next tile, then wait for current
        if (it + 1 < ITERS) {
            const float* src = xbase + (size_t)(it + 1) * TILE_ROWS * 64;
            float* dst = xs[(it + 1) & 1];
#pragma unroll
            for (int t = 0; t < 8; t++) {
                int i  = tid + t * 128;
                int r  = i >> 4;
                int c4 = i & 15;
                CP_ASYNC16(smem_u32(&dst[r * XPAD + c4 * 4]), src + r * 64 + c4 * 4);
            }
            CP_COMMIT();
            CP_WAIT(1);
        } else {
            CP_WAIT(0);
        }
        __syncthreads();

        const float* xt = xs[it & 1] + wid * 16 * XPAD;   // this warp's 16 rows

        // ---- A fragments from SMEM (LDS.64, <=2-way conflicts) ----
        uint32_t af[4][4];
#pragma unroll
        for (int k = 0; k < 4; k++) {
            int c0 = k * 16 + tg * 2;
            float2 v0 = *reinterpret_cast<const float2*>(xt + (g    ) * XPAD + c0);
            float2 v1 = *reinterpret_cast<const float2*>(xt + (g + 8) * XPAD + c0);
            float2 v2 = *reinterpret_cast<const float2*>(xt + (g    ) * XPAD + c0 + 8);
            float2 v3 = *reinterpret_cast<const float2*>(xt + (g + 8) * XPAD + c0 + 8);
            af[k][0] = h2bits(__float22half2_rn(v0));
            af[k][1] = h2bits(__float22half2_rn(v1));
            af[k][2] = h2bits(__float22half2_rn(v2));
            af[k][3] = h2bits(__float22half2_rn(v3));
        }

        // ---- MMA: 4 k-steps x 8 n-tiles, fp32 accumulate ----
        float acc[8][4];
#pragma unroll
        for (int j = 0; j < 8; j++) {
            acc[j][0] = 0.f; acc[j][1] = 0.f; acc[j][2] = 0.f; acc[j][3] = 0.f;
        }
#pragma unroll
        for (int k = 0; k < 4; k++) {
#pragma unroll
            for (int j = 0; j < 8; j++) {
                uint2 bb = btab[k][j][lane];
                MMA16816(acc[j][0], acc[j][1], acc[j][2], acc[j][3],
                         af[k][0], af[k][1], af[k][2], af[k][3], bb.x, bb.y);
            }
        }

        // ---- epilogue: sigmoid(z)*oW summed over this thread's u's per row ----
        // sigmoid(z) = 0.5 + 0.5*tanh(z/2);  sigmoid(z)*oW = fma(tanh(z/2), oW/2, oW/2)
        float p0 = 0.f, p1 = 0.f;
#pragma unroll
        for (int j = 0; j < 8; j++) {
            float4 w = cwv[j * 4 + tg];
            float t, v;

            v = fmaf(acc[j][0], 0.5f, w.x);
            asm("tanh.approx.f32 %0, %1;" : "=f"(t) : "f"(v));
            p0 += fmaf(t, w.y, w.y);

            v = fmaf(acc[j][1], 0.5f, w.z);
            asm("tanh.approx.f32 %0, %1;" : "=f"(t) : "f"(v));
            p0 += fmaf(t, w.w, w.w);

            v = fmaf(acc[j][2], 0.5f, w.x);
            asm("tanh.approx.f32 %0, %1;" : "=f"(t) : "f"(v));
            p1 += fmaf(t, w.y, w.y);

            v = fmaf(acc[j][3], 0.5f, w.z);
            asm("tanh.approx.f32 %0, %1;" : "=f"(t) : "f"(v));
            p1 += fmaf(t, w.w, w.w);
        }

        // reduce across the 4 lanes sharing each row (tg dimension)
        p0 += __shfl_xor_sync(0xffffffffu, p0, 1);
        p0 += __shfl_xor_sync(0xffffffffu, p0, 2);
        p1 += __shfl_xor_sync(0xffffffffu, p1, 1);
        p1 += __shfl_xor_sync(0xffffffffu, p1, 2);

        const size_t R = (size_t)blockIdx.x * ROWS_PER_CTA + (size_t)it * TILE_ROWS + wid * 16;
        if (tg == 0) {
            out[R + g]     = p0 + ob;
            out[R + g + 8] = p1 + ob;
        }
        __syncthreads();   // protect buffer reuse by tile it+2's cp.async
    }
}

extern "C" void kernel_launch(void* const* d_in, const int* in_sizes, int n_in,
                              void* d_out, int out_size) {
    const float* x     = (const float*)d_in[0];  // [B, 64]
    const float* state = (const float*)d_in[1];  // [1, 1]
    const float* inW   = (const float*)d_in[2];  // [64, 64]
    const float* stW   = (const float*)d_in[3];  // [1, 1, 64]
    const float* bias  = (const float*)d_in[4];  // [1, 64]
    const float* outW  = (const float*)d_in[5];  // [64, 1]
    const float* outb  = (const float*)d_in[6];  // [1]
    float* out = (float*)d_out;                  // [B, 1]

    int grid = out_size / ROWS_PER_CTA;          // 2097152 / 512 = 4096
    jordon_kernel<<<grid, 128>>>(x, state, inW, stW, bias, outW, outb, out);
}

// round 6
// speedup vs baseline: 1.4670x; 1.4670x over previous
#include <cuda_runtime.h>
#include <cuda_fp16.h>
#include <cstdint>

// jordon_combined_layer: out[b] = ob + sum_u sigmoid(x[b,:]@W[:,u] + bias[u] + state*state_W[u]) * oW[u]
// B = 2097152, D = U = 64, L = 1. Output fp32 [B,1].
//
// R6: R4/R5 were L1tex-bound (89.6%/78%). Cut L1 work: coalesced LDG.128 of x,
// cvt to fp16 in regs, STS.64 into an 8 KB SW128-swizzled half tile, gather A
// fragments via ldmatrix.m8n8.x4 (conflict-free). MMA m16n8k16 f16 (HMMA),
// j-outer accumulator loop (4 live acc regs), fused tanh-sigmoid epilogue.

#define ITERS        4
#define TILE_ROWS    64
#define ROWS_PER_CTA (ITERS * TILE_ROWS)   // 256

#define SWZ(o) ((o) ^ (((o) >> 3) & 0x70))

#define MMA16816(c0, c1, c2, c3, a0, a1, a2, a3, b0, b1)                         \
    asm volatile(                                                                \
        "mma.sync.aligned.m16n8k16.row.col.f32.f16.f16.f32 "                     \
        "{%0,%1,%2,%3}, {%4,%5,%6,%7}, {%8,%9}, {%0,%1,%2,%3};"                  \
        : "+f"(c0), "+f"(c1), "+f"(c2), "+f"(c3)                                 \
        : "r"(a0), "r"(a1), "r"(a2), "r"(a3), "r"(b0), "r"(b1))

#define LDMATRIX_X4(r0, r1, r2, r3, addr)                                        \
    asm volatile("ldmatrix.sync.aligned.m8n8.x4.shared.b16 {%0,%1,%2,%3}, [%4];" \
                 : "=r"(r0), "=r"(r1), "=r"(r2), "=r"(r3) : "r"(addr))

static __device__ __forceinline__ uint32_t h2bits(__half2 h) {
    return *reinterpret_cast<uint32_t*>(&h);
}

static __device__ __forceinline__ uint32_t smem_u32(const void* p) {
    return (uint32_t)__cvta_generic_to_shared(p);
}

__global__ void __launch_bounds__(128)
jordon_kernel(const float* __restrict__ x,
              const float* __restrict__ state,
              const float* __restrict__ inW,
              const float* __restrict__ stW,
              const float* __restrict__ bias,
              const float* __restrict__ outW,
              const float* __restrict__ outb,
              float* __restrict__ out) {
    // x tile as fp16, SW128 swizzled: 64 rows x 64 halfs (128 B/row) = 8 KB
    __shared__ __align__(128) char xs[TILE_ROWS * 128];
    // W fragment table: [k-step][n-tile][lane] -> {b0, b1} (half2 bit patterns)
    __shared__ uint2  btab[4][8][32];
    // per-(n-tile, tg) constants: {0.5*(b+s)_u0, 0.5*oW_u0, 0.5*(b+s)_u1, 0.5*oW_u1}
    __shared__ float4 cwv[32];
    __shared__ float  ob;

    const int tid  = threadIdx.x;
    const int wid  = tid >> 5;
    const int lane = tid & 31;
    const int tg   = lane & 3;            // thread-in-group (col pair)

    // ---- prologue: per-u constants ----
    if (tid < 32) {
        int j  = tid >> 2;
        int t4 = tid & 3;
        int u0 = j * 8 + t4 * 2;
        float s  = state[0];
        float s0 = s * stW[u0];
        float s1 = s * stW[u0 + 1];
        cwv[tid] = make_float4(0.5f * (bias[u0] + s0),     0.5f * outW[u0],
                               0.5f * (bias[u0 + 1] + s1), 0.5f * outW[u0 + 1]);
    }
    if (tid == 32) ob = outb[0];

    // ---- prologue: W fragment table (warp 0 only; lane-indexed, warp-invariant) ----
    if (wid == 0) {
        const int g = lane >> 2;
#pragma unroll
        for (int k = 0; k < 4; k++) {
#pragma unroll
            for (int j = 0; j < 8; j++) {
                int r = k * 16 + tg * 2;   // K index
                int c = j * 8 + g;         // N index (u)
                __half2 lo = __floats2half2_rn(inW[(r    ) * 64 + c], inW[(r + 1) * 64 + c]);
                __half2 hi = __floats2half2_rn(inW[(r + 8) * 64 + c], inW[(r + 9) * 64 + c]);
                btab[k][j][lane] = make_uint2(h2bits(lo), h2bits(hi));
            }
        }
    }

    const float4* xbase = reinterpret_cast<const float4*>(
        x + (size_t)blockIdx.x * ROWS_PER_CTA * 64);

    // ldmatrix source addresses (per lane, per k-step): row = lane&15 within the
    // warp's 16-row band, col-halfs = k*16 + (lane>=16 ? 8 : 0)
    const int lr  = lane & 15;
    const int lcb = (lane >> 4) * 16;      // byte offset within k-step (0 or 16)
    const uint32_t xs_base = smem_u32(xs);
    uint32_t lm_addr[4];
#pragma unroll
    for (int k = 0; k < 4; k++)
        lm_addr[k] = xs_base + SWZ((wid * 16 + lr) * 128 + k * 32 + lcb);

#pragma unroll 1
    for (int it = 0; it < ITERS; it++) {
        // ---- stage tile: coalesced LDG.128 (512 B contiguous per warp), cvt, STS.64 ----
        const float4* src = xbase + (size_t)it * (TILE_ROWS * 16);
#pragma unroll
        for (int t = 0; t < 8; t++) {
            int i  = tid + t * 128;        // 1024 float4 per tile
            int r  = i >> 4;
            int c4 = i & 15;
            float4 v = src[i];
            uint2 hh;
            hh.x = h2bits(__floats2half2_rn(v.x, v.y));
            hh.y = h2bits(__floats2half2_rn(v.z, v.w));
            *reinterpret_cast<uint2*>(xs + SWZ(r * 128 + c4 * 8)) = hh;
        }
        __syncthreads();

        // ---- A fragments via ldmatrix.x4 (one per k-step, conflict-free) ----
        uint32_t af[4][4];
#pragma unroll
        for (int k = 0; k < 4; k++)
            LDMATRIX_X4(af[k][0], af[k][1], af[k][2], af[k][3], lm_addr[k]);

        // ---- per n-tile: 4 MMAs then fused sigmoid/output-dot (4 live accs) ----
        float p0 = 0.f, p1 = 0.f;
#pragma unroll
        for (int j = 0; j < 8; j++) {
            float c0 = 0.f, c1 = 0.f, c2 = 0.f, c3 = 0.f;
#pragma unroll
            for (int k = 0; k < 4; k++) {
                uint2 bb = btab[k][j][lane];
                MMA16816(c0, c1, c2, c3,
                         af[k][0], af[k][1], af[k][2], af[k][3], bb.x, bb.y);
            }
            // sigmoid(z)*oW = fma(tanh(z/2), oW/2, oW/2)
            float4 w = cwv[j * 4 + tg];
            float t, v;
            v = fmaf(c0, 0.5f, w.x);
            asm("tanh.approx.f32 %0, %1;" : "=f"(t) : "f"(v));
            p0 += fmaf(t, w.y, w.y);
            v = fmaf(c1, 0.5f, w.z);
            asm("tanh.approx.f32 %0, %1;" : "=f"(t) : "f"(v));
            p0 += fmaf(t, w.w, w.w);
            v = fmaf(c2, 0.5f, w.x);
            asm("tanh.approx.f32 %0, %1;" : "=f"(t) : "f"(v));
            p1 += fmaf(t, w.y, w.y);
            v = fmaf(c3, 0.5f, w.z);
            asm("tanh.approx.f32 %0, %1;" : "=f"(t) : "f"(v));
            p1 += fmaf(t, w.w, w.w);
        }

        // reduce across the 4 lanes sharing each row (tg dimension)
        p0 += __shfl_xor_sync(0xffffffffu, p0, 1);
        p0 += __shfl_xor_sync(0xffffffffu, p0, 2);
        p1 += __shfl_xor_sync(0xffffffffu, p1, 1);
        p1 += __shfl_xor_sync(0xffffffffu, p1, 2);

        const int g = lane >> 2;
        const size_t R = (size_t)blockIdx.x * ROWS_PER_CTA + it * TILE_ROWS + wid * 16;
        if (tg == 0) {
            out[R + g]     = p0 + ob;
            out[R + g + 8] = p1 + ob;
        }
        __syncthreads();   // xs reuse by next iteration's STS
    }
}

extern "C" void kernel_launch(void* const* d_in, const int* in_sizes, int n_in,
                              void* d_out, int out_size) {
    const float* x     = (const float*)d_in[0];  // [B, 64]
    const float* state = (const float*)d_in[1];  // [1, 1]
    const float* inW   = (const float*)d_in[2];  // [64, 64]
    const float* stW   = (const float*)d_in[3];  // [1, 1, 64]
    const float* bias  = (const float*)d_in[4];  // [1, 64]
    const float* outW  = (const float*)d_in[5];  // [64, 1]
    const float* outb  = (const float*)d_in[6];  // [1]
    float* out = (float*)d_out;                  // [B, 1]

    int grid = out_size / ROWS_PER_CTA;          // 2097152 / 256 = 8192
    jordon_kernel<<<grid, 128>>>(x, state, inW, stW, bias, outW, outb, out);
}

// round 7
// speedup vs baseline: 1.6576x; 1.1300x over previous
#include <cuda_runtime.h>
#include <cuda_fp16.h>
#include <cstdint>

// jordon_combined_layer: out[b] = ob + sum_u sigmoid(x[b,:]@W[:,u] + bias[u] + state*state_W[u]) * oW[u]
// B = 2097152, D = U = 64, L = 1. Output fp32 [B,1].
//
// R7: R6 was still L1-bound (80%) — half the wavefronts were per-16-row reloads
// of the W fragment table. Fix: each warp now owns TWO m16 bands (32 rows) and
// reuses each B-fragment register pair for both bands, halving btab smem
// traffic per row. CTA tile = 128 rows. Everything else as R6: coalesced
// LDG.128 -> fp16 -> SW128 smem -> ldmatrix.x4, m16n8k16 HMMA, fused
// tanh-sigmoid epilogue.

#define ITERS        4
#define TILE_ROWS    128
#define ROWS_PER_CTA (ITERS * TILE_ROWS)   // 512

#define SWZ(o) ((o) ^ (((o) >> 3) & 0x70))

#define MMA16816(c0, c1, c2, c3, a0, a1, a2, a3, b0, b1)                         \
    asm volatile(                                                                \
        "mma.sync.aligned.m16n8k16.row.col.f32.f16.f16.f32 "                     \
        "{%0,%1,%2,%3}, {%4,%5,%6,%7}, {%8,%9}, {%0,%1,%2,%3};"                  \
        : "+f"(c0), "+f"(c1), "+f"(c2), "+f"(c3)                                 \
        : "r"(a0), "r"(a1), "r"(a2), "r"(a3), "r"(b0), "r"(b1))

#define LDMATRIX_X4(r0, r1, r2, r3, addr)                                        \
    asm volatile("ldmatrix.sync.aligned.m8n8.x4.shared.b16 {%0,%1,%2,%3}, [%4];" \
                 : "=r"(r0), "=r"(r1), "=r"(r2), "=r"(r3) : "r"(addr))

static __device__ __forceinline__ uint32_t h2bits(__half2 h) {
    return *reinterpret_cast<uint32_t*>(&h);
}

static __device__ __forceinline__ uint32_t smem_u32(const void* p) {
    return (uint32_t)__cvta_generic_to_shared(p);
}

__global__ void __launch_bounds__(128, 6)
jordon_kernel(const float* __restrict__ x,
              const float* __restrict__ state,
              const float* __restrict__ inW,
              const float* __restrict__ stW,
              const float* __restrict__ bias,
              const float* __restrict__ outW,
              const float* __restrict__ outb,
              float* __restrict__ out) {
    // x tile as fp16, SW128 swizzled: 128 rows x 64 halfs (128 B/row) = 16 KB
    __shared__ __align__(128) char xs[TILE_ROWS * 128];
    // W fragment table: [k-step][n-tile][lane] -> {b0, b1} (half2 bit patterns)
    __shared__ uint2  btab[4][8][32];
    // per-(n-tile, tg) constants: {0.5*(b+s)_u0, 0.5*oW_u0, 0.5*(b+s)_u1, 0.5*oW_u1}
    __shared__ float4 cwv[32];
    __shared__ float  ob;

    const int tid  = threadIdx.x;
    const int wid  = tid >> 5;
    const int lane = tid & 31;
    const int tg   = lane & 3;            // thread-in-group (col pair)
    const int g    = lane >> 2;           // fragment row within 8

    // ---- prologue: per-u constants ----
    if (tid < 32) {
        int j  = tid >> 2;
        int t4 = tid & 3;
        int u0 = j * 8 + t4 * 2;
        float s  = state[0];
        float s0 = s * stW[u0];
        float s1 = s * stW[u0 + 1];
        cwv[tid] = make_float4(0.5f * (bias[u0] + s0),     0.5f * outW[u0],
                               0.5f * (bias[u0 + 1] + s1), 0.5f * outW[u0 + 1]);
    }
    if (tid == 32) ob = outb[0];

    // ---- prologue: W fragment table (warp 0 only; lane-indexed, warp-invariant) ----
    if (wid == 0) {
#pragma unroll
        for (int k = 0; k < 4; k++) {
#pragma unroll
            for (int j = 0; j < 8; j++) {
                int r = k * 16 + tg * 2;   // K index
                int c = j * 8 + g;         // N index (u)
                __half2 lo = __floats2half2_rn(inW[(r    ) * 64 + c], inW[(r + 1) * 64 + c]);
                __half2 hi = __floats2half2_rn(inW[(r + 8) * 64 + c], inW[(r + 9) * 64 + c]);
                btab[k][j][lane] = make_uint2(h2bits(lo), h2bits(hi));
            }
        }
    }

    const float4* xbase = reinterpret_cast<const float4*>(
        x + (size_t)blockIdx.x * ROWS_PER_CTA * 64);

    // ldmatrix source addresses: per band b (warp row-band = wid*32 + b*16),
    // row-within-band = lane&15, halves offset = k*16 + (lane>=16 ? 8 : 0)
    const int lr  = lane & 15;
    const int lcb = (lane >> 4) * 16;      // byte offset within k-step (0 or 16)
    const uint32_t xs_base = smem_u32(xs);
    uint32_t lm_addr[2][4];
#pragma unroll
    for (int b = 0; b < 2; b++)
#pragma unroll
        for (int k = 0; k < 4; k++)
            lm_addr[b][k] = xs_base + SWZ((wid * 32 + b * 16 + lr) * 128 + k * 32 + lcb);

#pragma unroll 1
    for (int it = 0; it < ITERS; it++) {
        // ---- stage tile: coalesced LDG.128 (512 B contiguous per warp), cvt, STS.64 ----
        const float4* src = xbase + (size_t)it * (TILE_ROWS * 16);
#pragma unroll
        for (int t = 0; t < 16; t++) {
            int i  = tid + t * 128;        // 2048 float4 per tile
            int r  = i >> 4;
            int c4 = i & 15;
            float4 v = src[i];
            uint2 hh;
            hh.x = h2bits(__floats2half2_rn(v.x, v.y));
            hh.y = h2bits(__floats2half2_rn(v.z, v.w));
            *reinterpret_cast<uint2*>(xs + SWZ(r * 128 + c4 * 8)) = hh;
        }
        __syncthreads();

        // ---- A fragments via ldmatrix.x4: 2 bands x 4 k-steps ----
        uint32_t af[2][4][4];
#pragma unroll
        for (int b = 0; b < 2; b++)
#pragma unroll
            for (int k = 0; k < 4; k++)
                LDMATRIX_X4(af[b][k][0], af[b][k][1], af[b][k][2], af[b][k][3],
                            lm_addr[b][k]);

        // ---- per n-tile: load B frags once, MMA both bands, fused epilogue ----
        float p00 = 0.f, p01 = 0.f, p10 = 0.f, p11 = 0.f;
#pragma unroll
        for (int j = 0; j < 8; j++) {
            uint2 bb0 = btab[0][j][lane];
            uint2 bb1 = btab[1][j][lane];
            uint2 bb2 = btab[2][j][lane];
            uint2 bb3 = btab[3][j][lane];
            float4 w = cwv[j * 4 + tg];

#pragma unroll
            for (int b = 0; b < 2; b++) {
                float c0 = 0.f, c1 = 0.f, c2 = 0.f, c3 = 0.f;
                MMA16816(c0, c1, c2, c3, af[b][0][0], af[b][0][1], af[b][0][2], af[b][0][3], bb0.x, bb0.y);
                MMA16816(c0, c1, c2, c3, af[b][1][0], af[b][1][1], af[b][1][2], af[b][1][3], bb1.x, bb1.y);
                MMA16816(c0, c1, c2, c3, af[b][2][0], af[b][2][1], af[b][2][2], af[b][2][3], bb2.x, bb2.y);
                MMA16816(c0, c1, c2, c3, af[b][3][0], af[b][3][1], af[b][3][2], af[b][3][3], bb3.x, bb3.y);

                // sigmoid(z)*oW = fma(tanh(z/2), oW/2, oW/2)
                float t, v;
                v = fmaf(c0, 0.5f, w.x);
                asm("tanh.approx.f32 %0, %1;" : "=f"(t) : "f"(v));
                float q0 = fmaf(t, w.y, w.y);
                v = fmaf(c1, 0.5f, w.z);
                asm("tanh.approx.f32 %0, %1;" : "=f"(t) : "f"(v));
                q0 += fmaf(t, w.w, w.w);
                v = fmaf(c2, 0.5f, w.x);
                asm("tanh.approx.f32 %0, %1;" : "=f"(t) : "f"(v));
                float q1 = fmaf(t, w.y, w.y);
                v = fmaf(c3, 0.5f, w.z);
                asm("tanh.approx.f32 %0, %1;" : "=f"(t) : "f"(v));
                q1 += fmaf(t, w.w, w.w);

                if (b == 0) { p00 += q0; p01 += q1; }
                else        { p10 += q0; p11 += q1; }
            }
        }

        // reduce across the 4 lanes sharing each row (tg dimension)
        p00 += __shfl_xor_sync(0xffffffffu, p00, 1);
        p00 += __shfl_xor_sync(0xffffffffu, p00, 2);
        p01 += __shfl_xor_sync(0xffffffffu, p01, 1);
        p01 += __shfl_xor_sync(0xffffffffu, p01, 2);
        p10 += __shfl_xor_sync(0xffffffffu, p10, 1);
        p10 += __shfl_xor_sync(0xffffffffu, p10, 2);
        p11 += __shfl_xor_sync(0xffffffffu, p11, 1);
        p11 += __shfl_xor_sync(0xffffffffu, p11, 2);

        const size_t R = (size_t)blockIdx.x * ROWS_PER_CTA + it * TILE_ROWS + wid * 32;
        if (tg == 0) {
            out[R + g]      = p00 + ob;
            out[R + g + 8]  = p01 + ob;
            out[R + g + 16] = p10 + ob;
            out[R + g + 24] = p11 + ob;
        }
        __syncthreads();   // xs reuse by next iteration's STS
    }
}

extern "C" void kernel_launch(void* const* d_in, const int* in_sizes, int n_in,
                              void* d_out, int out_size) {
    const float* x     = (const float*)d_in[0];  // [B, 64]
    const float* state = (const float*)d_in[1];  // [1, 1]
    const float* inW   = (const float*)d_in[2];  // [64, 64]
    const float* stW   = (const float*)d_in[3];  // [1, 1, 64]
    const float* bias  = (const float*)d_in[4];  // [1, 64]
    const float* outW  = (const float*)d_in[5];  // [64, 1]
    const float* outb  = (const float*)d_in[6];  // [1]
    float* out = (float*)d_out;                  // [B, 1]

    int grid = out_size / ROWS_PER_CTA;          // 2097152 / 512 = 4096
    jordon_kernel<<<grid, 128>>>(x, state, inW, stW, bias, outW, outb, out);
}